// round 2
// baseline (speedup 1.0000x reference)
#include <cuda_runtime.h>

#define MAXN 400000
#define BN_EPS 1e-4f

// ---------------- scratch (device globals; no allocations allowed) ----------
__device__ float g_xv  [(size_t)MAXN * 32];
__device__ float g_e0  [(size_t)MAXN * 32];
__device__ float g_down[(size_t)MAXN * 64];
__device__ float g_e1  [(size_t)MAXN * 64];
__device__ float g_up  [(size_t)MAXN * 32];
__device__ float g_dec [(size_t)MAXN * 32];
// 3 batchnorms, each: [0:64) = column sums, [64:128) = column sum-of-squares
__device__ float g_bn[3 * 128];

// ---------------- zero scratch (down buffer + bn accumulators) --------------
__global__ void zero_scratch(long m64) {
    long i = (long)blockIdx.x * blockDim.x + threadIdx.x;
    long stride = (long)gridDim.x * blockDim.x;
    for (; i < m64; i += stride) g_down[i] = 0.0f;
    if (blockIdx.x == 0) {
        for (int j = threadIdx.x; j < 3 * 128; j += blockDim.x) g_bn[j] = 0.0f;
    }
}

// ---------------- subconv 3 -> 32 (input features) ---------------------------
__global__ void subconv3_32(const float* __restrict__ feat,
                            const int* __restrict__ nbr,
                            const float* __restrict__ W,
                            float* __restrict__ out, int n) {
    int w = (int)((blockIdx.x * blockDim.x + threadIdx.x) >> 5);
    int lane = threadIdx.x & 31;
    if (w >= n) return;
    float acc = 0.0f;
    const int* nb = nbr + (long)w * 27;
    #pragma unroll 1
    for (int k = 0; k < 27; k++) {
        int idx = nb[k];
        if (idx < 0) continue;
        float f0 = __ldg(&feat[(long)idx * 3 + 0]);
        float f1 = __ldg(&feat[(long)idx * 3 + 1]);
        float f2 = __ldg(&feat[(long)idx * 3 + 2]);
        const float* Wk = W + k * 96;
        acc += f0 * Wk[lane] + f1 * Wk[32 + lane] + f2 * Wk[64 + lane];
    }
    out[(long)w * 32 + lane] = acc;
}

// ---------------- generic subconv: CIN = CINCH*32, COUT = NACC*32 -----------
// CONCAT: input channels 0..31 from fA (row stride 32), 32..63 from fB.
template<int CINCH, int NACC, bool CONCAT>
__global__ void subconv_k(const float* __restrict__ fA,
                          const float* __restrict__ fB,
                          const int* __restrict__ nbr,
                          const float* __restrict__ W,
                          float* __restrict__ out, int n) {
    int w = (int)((blockIdx.x * blockDim.x + threadIdx.x) >> 5);
    int lane = threadIdx.x & 31;
    if (w >= n) return;
    constexpr int CIN = CINCH * 32;
    constexpr int COUT = NACC * 32;
    float acc[NACC];
    #pragma unroll
    for (int j = 0; j < NACC; j++) acc[j] = 0.0f;
    const int* nb = nbr + (long)w * 27;
    #pragma unroll 1
    for (int k = 0; k < 27; k++) {
        int idx = nb[k];
        if (idx < 0) continue;
        const float* Wk = W + (long)k * CIN * COUT;
        #pragma unroll
        for (int ch = 0; ch < CINCH; ch++) {
            float f;
            if (CONCAT)
                f = (ch == 0 ? fA : fB)[(long)idx * 32 + lane];
            else
                f = fA[(long)idx * CIN + ch * 32 + lane];
            const float* Wc = Wk + ch * 32 * COUT;
            #pragma unroll
            for (int ci = 0; ci < 32; ci++) {
                float v = __shfl_sync(0xffffffffu, f, ci);
                #pragma unroll
                for (int j = 0; j < NACC; j++)
                    acc[j] += v * Wc[ci * COUT + j * 32 + lane];
            }
        }
    }
    #pragma unroll
    for (int j = 0; j < NACC; j++)
        out[(long)w * COUT + j * 32 + lane] = acc[j];
}

// ---------------- down: segment_sum(e0 @ W_down[child_off], parent_id) ------
__global__ void down_kernel(const float* __restrict__ e0,
                            const int* __restrict__ parent,
                            const int* __restrict__ coff,
                            const float* __restrict__ Wd,
                            float* __restrict__ down, int n) {
    int w = (int)((blockIdx.x * blockDim.x + threadIdx.x) >> 5);
    int lane = threadIdx.x & 31;
    if (w >= n) return;
    float f = e0[(long)w * 32 + lane];
    const float* Wc = Wd + (long)coff[w] * 2048;   // [32,64]
    float a0 = 0.0f, a1 = 0.0f;
    #pragma unroll
    for (int ci = 0; ci < 32; ci++) {
        float v = __shfl_sync(0xffffffffu, f, ci);
        a0 += v * Wc[ci * 64 + lane];
        a1 += v * Wc[ci * 64 + 32 + lane];
    }
    int p = parent[w];
    atomicAdd(&down[(long)p * 64 + lane], a0);
    atomicAdd(&down[(long)p * 64 + 32 + lane], a1);
}

// ---------------- up: e1[parent] @ W_up[child_off] ---------------------------
__global__ void up_kernel(const float* __restrict__ e1,
                          const int* __restrict__ parent,
                          const int* __restrict__ coff,
                          const float* __restrict__ Wu,
                          float* __restrict__ up, int n) {
    int w = (int)((blockIdx.x * blockDim.x + threadIdx.x) >> 5);
    int lane = threadIdx.x & 31;
    if (w >= n) return;
    int p = parent[w];
    float f0 = e1[(long)p * 64 + lane];
    float f1 = e1[(long)p * 64 + 32 + lane];
    const float* Wc = Wu + (long)coff[w] * 2048;   // [64,32]
    float a = 0.0f;
    #pragma unroll
    for (int ci = 0; ci < 32; ci++)
        a += __shfl_sync(0xffffffffu, f0, ci) * Wc[ci * 32 + lane];
    #pragma unroll
    for (int ci = 0; ci < 32; ci++)
        a += __shfl_sync(0xffffffffu, f1, ci) * Wc[(32 + ci) * 32 + lane];
    up[(long)w * 32 + lane] = a;
}

// ---------------- batchnorm stats (column sum / sumsq) -----------------------
// C must be power of two (32 or 64). blockDim = 256.
__global__ void bn_stats(const float* __restrict__ x, int bnid, int C, int n) {
    int tid = threadIdx.x;
    int c = tid & (C - 1);
    int rpb = 256 / C;
    float s = 0.0f, q = 0.0f;
    for (long r = (long)blockIdx.x * rpb + tid / C; r < n;
         r += (long)gridDim.x * rpb) {
        float v = x[r * C + c];
        s += v; q += v * v;
    }
    __shared__ float ss[64], sq[64];
    if (tid < 64) { ss[tid] = 0.0f; sq[tid] = 0.0f; }
    __syncthreads();
    atomicAdd(&ss[c], s);
    atomicAdd(&sq[c], q);
    __syncthreads();
    if (tid < C) {
        atomicAdd(&g_bn[bnid * 128 + tid], ss[tid]);
        atomicAdd(&g_bn[bnid * 128 + 64 + tid], sq[tid]);
    }
}

// ---------------- batchnorm apply + relu (in place) --------------------------
__global__ void bn_apply(float* __restrict__ x,
                         const float* __restrict__ g,
                         const float* __restrict__ b,
                         int bnid, int C, int n) {
    float inv_n = 1.0f / (float)n;
    long total = (long)n * C;
    long stride = (long)gridDim.x * blockDim.x;
    for (long i = (long)blockIdx.x * blockDim.x + threadIdx.x; i < total; i += stride) {
        int c = (int)(i & (C - 1));
        float mu = g_bn[bnid * 128 + c] * inv_n;
        float var = g_bn[bnid * 128 + 64 + c] * inv_n - mu * mu;
        float v = (x[i] - mu) * rsqrtf(var + BN_EPS) * g[c] + b[c];
        x[i] = v > 0.0f ? v : 0.0f;
    }
}

// ---------------- final: bnrelu(dec) -> feature; y = feature@W_lin + b ------
__global__ void final_kernel(const float* __restrict__ dec,
                             const float* __restrict__ g,
                             const float* __restrict__ b,
                             const float* __restrict__ Wlin,
                             const float* __restrict__ blin,
                             float* __restrict__ y,
                             float* __restrict__ fout, int n) {
    int w = (int)((blockIdx.x * blockDim.x + threadIdx.x) >> 5);
    int lane = threadIdx.x & 31;
    if (w >= n) return;
    float inv_n = 1.0f / (float)n;
    float mu = g_bn[2 * 128 + lane] * inv_n;
    float var = g_bn[2 * 128 + 64 + lane] * inv_n - mu * mu;
    float f = (dec[(long)w * 32 + lane] - mu) * rsqrtf(var + BN_EPS) * g[lane] + b[lane];
    f = f > 0.0f ? f : 0.0f;
    fout[(long)w * 32 + lane] = f;
    float acc = (lane < 20) ? blin[lane] : 0.0f;
    #pragma unroll
    for (int ci = 0; ci < 32; ci++) {
        float v = __shfl_sync(0xffffffffu, f, ci);
        if (lane < 20) acc += v * Wlin[ci * 20 + lane];
    }
    if (lane < 20) y[(long)w * 20 + lane] = acc;
}

// ---------------- launcher ---------------------------------------------------
extern "C" void kernel_launch(void* const* d_in, const int* in_sizes, int n_in,
                              void* d_out, int out_size) {
    const float* feats      = (const float*)d_in[0];
    const int*   nbr_fine   = (const int*)  d_in[1];
    const int*   nbr_coarse = (const int*)  d_in[2];
    const int*   parent     = (const int*)  d_in[3];
    const int*   coff       = (const int*)  d_in[4];
    const float* W_sub      = (const float*)d_in[5];
    const float* W_e0       = (const float*)d_in[6];
    const float* g0         = (const float*)d_in[7];
    const float* b0         = (const float*)d_in[8];
    const float* W_down     = (const float*)d_in[9];
    const float* W_e1       = (const float*)d_in[10];
    const float* g1         = (const float*)d_in[11];
    const float* b1         = (const float*)d_in[12];
    const float* W_up       = (const float*)d_in[13];
    const float* W_dec      = (const float*)d_in[14];
    const float* g_outp     = (const float*)d_in[15];
    const float* b_outp     = (const float*)d_in[16];
    const float* W_lin      = (const float*)d_in[17];
    const float* b_lin      = (const float*)d_in[18];

    int N = in_sizes[0] / 3;
    int M = in_sizes[2] / 27;

    float* y    = (float*)d_out;
    float* fout = y + (long)N * 20;

    float *p_xv, *p_e0, *p_down, *p_e1, *p_up, *p_dec;
    cudaGetSymbolAddress((void**)&p_xv,   g_xv);
    cudaGetSymbolAddress((void**)&p_e0,   g_e0);
    cudaGetSymbolAddress((void**)&p_down, g_down);
    cudaGetSymbolAddress((void**)&p_e1,   g_e1);
    cudaGetSymbolAddress((void**)&p_up,   g_up);
    cudaGetSymbolAddress((void**)&p_dec,  g_dec);

    const int WPB = 8;               // warps per block (blockDim 256)
    dim3 blk(256);
    int gridN = (N + WPB - 1) / WPB;
    int gridM = (M + WPB - 1) / WPB;

    zero_scratch<<<512, 256>>>((long)M * 64);

    // encoder fine level
    subconv3_32<<<gridN, blk>>>(feats, nbr_fine, W_sub, p_xv, N);
    subconv_k<1, 1, false><<<gridN, blk>>>(p_xv, nullptr, nbr_fine, W_e0, p_e0, N);
    bn_stats<<<1184, 256>>>(p_e0, 0, 32, N);
    bn_apply<<<1184, 256>>>(p_e0, g0, b0, 0, 32, N);

    // down + coarse level
    down_kernel<<<gridN, blk>>>(p_e0, parent, coff, W_down, p_down, N);
    subconv_k<2, 2, false><<<gridM, blk>>>(p_down, nullptr, nbr_coarse, W_e1, p_e1, M);
    bn_stats<<<1184, 256>>>(p_e1, 1, 64, M);
    bn_apply<<<1184, 256>>>(p_e1, g1, b1, 1, 64, M);

    // up + decoder
    up_kernel<<<gridN, blk>>>(p_e1, parent, coff, W_up, p_up, N);
    subconv_k<2, 1, true><<<gridN, blk>>>(p_e0, p_up, nbr_fine, W_dec, p_dec, N);
    bn_stats<<<1184, 256>>>(p_dec, 2, 32, N);

    // fused bnrelu + linear head, writes both outputs
    final_kernel<<<gridN, blk>>>(p_dec, g_outp, b_outp, W_lin, b_lin, y, fout, N);
}

// round 3
// speedup vs baseline: 1.0983x; 1.0983x over previous
#include <cuda_runtime.h>

#define MAXN 400000
#define MAXPAIR (MAXN * 26)
#define BN_EPS 1e-4f
#define FULLM 0xffffffffu

// ---------------- scratch (device globals; no allocations allowed) ----------
__device__ float g_xv  [(size_t)MAXN * 32];
__device__ float g_e0  [(size_t)MAXN * 32];
__device__ float g_down[(size_t)MAXN * 64];
__device__ float g_e1  [(size_t)MAXN * 64];
__device__ float g_up  [(size_t)MAXN * 32];
__device__ float g_dec [(size_t)MAXN * 32];
__device__ float g_bn[3 * 128];            // per-bn: [0:64) sums, [64:128) sumsq

__device__ int2          g_pf [MAXPAIR];   // fine pairs (dst, src), grouped by k
__device__ unsigned char g_pfk[MAXPAIR];
__device__ int2          g_pc [MAXPAIR];   // coarse pairs
__device__ unsigned char g_pck[MAXPAIR];
__device__ int g_cnt[64];                  // [lvl*32 + k] histogram
__device__ int g_off[64];
__device__ int g_cur[64];
__device__ int g_np [2];                   // total pairs per level

// ---------------- f32x2 helpers ---------------------------------------------
__device__ __forceinline__ unsigned long long pk2(float x, float y) {
    unsigned long long r;
    asm("mov.b64 %0, {%1, %2};" : "=l"(r) : "f"(x), "f"(y));
    return r;
}
__device__ __forceinline__ unsigned long long fma2(unsigned long long a,
                                                   unsigned long long b,
                                                   unsigned long long c) {
    unsigned long long d;
    asm("fma.rn.f32x2 %0, %1, %2, %3;" : "=l"(d) : "l"(a), "l"(b), "l"(c));
    return d;
}
__device__ __forceinline__ void unpk2(unsigned long long a, float& x, float& y) {
    asm("mov.b64 {%0, %1}, %2;" : "=f"(x), "=f"(y) : "l"(a));
}

// ---------------- zero: g_down rows, bn accumulators, histograms ------------
__global__ void zero_kernel(int m) {
    int tid = blockIdx.x * blockDim.x + threadIdx.x;
    int stride = gridDim.x * blockDim.x;
    float4* d4 = (float4*)g_down;
    int n4 = m * 16;
    for (int i = tid; i < n4; i += stride) d4[i] = make_float4(0.f, 0.f, 0.f, 0.f);
    if (blockIdx.x == 0 && threadIdx.x < 128) {
        g_bn[threadIdx.x] = 0.f; g_bn[128 + threadIdx.x] = 0.f; g_bn[256 + threadIdx.x] = 0.f;
        if (threadIdx.x < 64) g_cnt[threadIdx.x] = 0;
    }
}

// ---------------- pair building ----------------------------------------------
__global__ void hist_pairs(const int* __restrict__ nbr, int n27, int lvl) {
    __shared__ int sh[27];
    if (threadIdx.x < 27) sh[threadIdx.x] = 0;
    __syncthreads();
    int tid = blockIdx.x * blockDim.x + threadIdx.x;
    int stride = gridDim.x * blockDim.x;
    for (int i = tid; i < n27; i += stride) {
        int k = i % 27;
        if (k != 13 && nbr[i] >= 0) atomicAdd(&sh[k], 1);
    }
    __syncthreads();
    if (threadIdx.x < 27) atomicAdd(&g_cnt[lvl * 32 + threadIdx.x], sh[threadIdx.x]);
}

__global__ void scan_kernel() {
    if (blockIdx.x == 0 && threadIdx.x == 0) {
        for (int l = 0; l < 2; l++) {
            int s = 0;
            for (int k = 0; k < 27; k++) {
                g_off[l * 32 + k] = s; g_cur[l * 32 + k] = s;
                s += g_cnt[l * 32 + k];
            }
            g_np[l] = s;
        }
    }
}

__global__ void fill_pairs(const int* __restrict__ nbr, int n27, int lvl,
                           int2* __restrict__ pairs, unsigned char* __restrict__ pk) {
    int tid = blockIdx.x * blockDim.x + threadIdx.x;
    int stride = gridDim.x * blockDim.x;
    for (int i = tid; i < n27; i += stride) {
        int k = i % 27;
        int idx = nbr[i];
        if (k != 13 && idx >= 0) {
            int pos = atomicAdd(&g_cur[lvl * 32 + k], 1);
            pairs[pos] = make_int2(i / 27, idx);
            pk[pos] = (unsigned char)k;
        }
    }
}

// ---------------- conv 3->32 -------------------------------------------------
__global__ void conv3_center(const float* __restrict__ in, const float* __restrict__ W,
                             float* __restrict__ out, int n) {
    int gw = (blockIdx.x * blockDim.x + threadIdx.x) >> 5;
    int lane = threadIdx.x & 31;
    int nw = (gridDim.x * blockDim.x) >> 5;
    float w0 = __ldg(&W[(13 * 3 + 0) * 32 + lane]);
    float w1 = __ldg(&W[(13 * 3 + 1) * 32 + lane]);
    float w2 = __ldg(&W[(13 * 3 + 2) * 32 + lane]);
    for (int v = gw; v < n; v += nw) {
        float f = (lane < 3) ? __ldg(&in[v * 3 + lane]) : 0.f;
        float a = __shfl_sync(FULLM, f, 0) * w0;
        a = fmaf(__shfl_sync(FULLM, f, 1), w1, a);
        a = fmaf(__shfl_sync(FULLM, f, 2), w2, a);
        out[v * 32 + lane] = a;
    }
}

__global__ void conv3_pair(const float* __restrict__ in, const float* __restrict__ W,
                           float* __restrict__ out, const int2* __restrict__ pairs,
                           const unsigned char* __restrict__ pk, const int* __restrict__ npp) {
    int gw = (blockIdx.x * blockDim.x + threadIdx.x) >> 5;
    int lane = threadIdx.x & 31;
    int nw = (gridDim.x * blockDim.x) >> 5;
    int np = *npp;
    float w0 = 0.f, w1 = 0.f, w2 = 0.f;
    int kcur = -1;
    const int PPW = 32;
    for (int base = gw * PPW; base < np; base += nw * PPW) {
        int cnt = min(PPW, np - base);
        for (int m = 0; m < cnt; m++) {
            int2 pr = pairs[base + m];
            int k = pk[base + m];
            if (k != kcur) {
                kcur = k;
                w0 = __ldg(&W[(k * 3 + 0) * 32 + lane]);
                w1 = __ldg(&W[(k * 3 + 1) * 32 + lane]);
                w2 = __ldg(&W[(k * 3 + 2) * 32 + lane]);
            }
            float f = (lane < 3) ? __ldg(&in[pr.y * 3 + lane]) : 0.f;
            float a = __shfl_sync(FULLM, f, 0) * w0;
            a = fmaf(__shfl_sync(FULLM, f, 1), w1, a);
            a = fmaf(__shfl_sync(FULLM, f, 2), w2, a);
            atomicAdd(&out[pr.x * 32 + lane], a);
        }
    }
}

// ---------------- conv 32->32 ------------------------------------------------
__global__ void conv32_center(const float* __restrict__ in, const float* __restrict__ W,
                              float* __restrict__ out, int n) {
    int gw = (blockIdx.x * blockDim.x + threadIdx.x) >> 5;
    int lane = threadIdx.x & 31;
    int nw = (gridDim.x * blockDim.x) >> 5;
    float w[32];
    #pragma unroll
    for (int ci = 0; ci < 32; ci++) w[ci] = __ldg(&W[(13 * 32 + ci) * 32 + lane]);
    for (int v = gw; v < n; v += nw) {
        float f = __ldg(&in[v * 32 + lane]);
        float acc = 0.f;
        #pragma unroll
        for (int ci = 0; ci < 32; ci++) acc = fmaf(__shfl_sync(FULLM, f, ci), w[ci], acc);
        out[v * 32 + lane] = acc;
    }
}

__global__ void conv32_pair(const float* __restrict__ in, const float* __restrict__ W,
                            float* __restrict__ out, const int2* __restrict__ pairs,
                            const unsigned char* __restrict__ pk, const int* __restrict__ npp) {
    int gw = (blockIdx.x * blockDim.x + threadIdx.x) >> 5;
    int lane = threadIdx.x & 31;
    int nw = (gridDim.x * blockDim.x) >> 5;
    int np = *npp;
    float w[32];
    int kcur = -1;
    const int PPW = 32;
    for (int base = gw * PPW; base < np; base += nw * PPW) {
        int cnt = min(PPW, np - base);
        int2 pr = pairs[base];
        int k = pk[base];
        float f = __ldg(&in[pr.y * 32 + lane]);
        for (int m = 0; m < cnt; m++) {
            int2 prn = make_int2(0, 0); int kn = 0; float fn = 0.f;
            if (m + 1 < cnt) {
                prn = pairs[base + m + 1];
                kn = pk[base + m + 1];
                fn = __ldg(&in[prn.y * 32 + lane]);
            }
            if (k != kcur) {
                kcur = k;
                #pragma unroll
                for (int ci = 0; ci < 32; ci++) w[ci] = __ldg(&W[(k * 32 + ci) * 32 + lane]);
            }
            float acc = 0.f;
            #pragma unroll
            for (int ci = 0; ci < 32; ci++) acc = fmaf(__shfl_sync(FULLM, f, ci), w[ci], acc);
            atomicAdd(&out[pr.x * 32 + lane], acc);
            pr = prn; k = kn; f = fn;
        }
    }
}

// ---------------- conv 64->64 (coarse), f32x2 packed -------------------------
// lane owns output channels {lane, lane+32}; w2[ci] = {W[ci][lane], W[ci][lane+32]}
__global__ void __launch_bounds__(128)
conv64_center(const float* __restrict__ in, const float* __restrict__ W,
              float* __restrict__ out, int n) {
    int gw = (blockIdx.x * blockDim.x + threadIdx.x) >> 5;
    int lane = threadIdx.x & 31;
    int nw = (gridDim.x * blockDim.x) >> 5;
    unsigned long long w2[64];
    #pragma unroll
    for (int ci = 0; ci < 64; ci++) {
        float a = __ldg(&W[(13 * 64 + ci) * 64 + lane]);
        float b = __ldg(&W[(13 * 64 + ci) * 64 + 32 + lane]);
        w2[ci] = pk2(a, b);
    }
    for (int v = gw; v < n; v += nw) {
        float2 fv = *(const float2*)(in + v * 64 + 2 * lane);
        unsigned long long acc = pk2(0.f, 0.f);
        #pragma unroll
        for (int j = 0; j < 32; j++) {
            float va = __shfl_sync(FULLM, fv.x, j);
            float vb = __shfl_sync(FULLM, fv.y, j);
            acc = fma2(pk2(va, va), w2[2 * j], acc);
            acc = fma2(pk2(vb, vb), w2[2 * j + 1], acc);
        }
        float r0, r1; unpk2(acc, r0, r1);
        out[v * 64 + lane] = r0;
        out[v * 64 + 32 + lane] = r1;
    }
}

__global__ void __launch_bounds__(128)
conv64_pair(const float* __restrict__ in, const float* __restrict__ W,
            float* __restrict__ out, const int2* __restrict__ pairs,
            const unsigned char* __restrict__ pk, const int* __restrict__ npp) {
    int gw = (blockIdx.x * blockDim.x + threadIdx.x) >> 5;
    int lane = threadIdx.x & 31;
    int nw = (gridDim.x * blockDim.x) >> 5;
    int np = *npp;
    unsigned long long w2[64];
    int kcur = -1;
    const int PPW = 32;
    for (int base = gw * PPW; base < np; base += nw * PPW) {
        int cnt = min(PPW, np - base);
        int2 pr = pairs[base];
        int k = pk[base];
        float2 fv = *(const float2*)(in + pr.y * 64 + 2 * lane);
        for (int m = 0; m < cnt; m++) {
            int2 prn = make_int2(0, 0); int kn = 0; float2 fvn = make_float2(0.f, 0.f);
            if (m + 1 < cnt) {
                prn = pairs[base + m + 1];
                kn = pk[base + m + 1];
                fvn = *(const float2*)(in + prn.y * 64 + 2 * lane);
            }
            if (k != kcur) {
                kcur = k;
                #pragma unroll
                for (int ci = 0; ci < 64; ci++) {
                    float a = __ldg(&W[(k * 64 + ci) * 64 + lane]);
                    float b = __ldg(&W[(k * 64 + ci) * 64 + 32 + lane]);
                    w2[ci] = pk2(a, b);
                }
            }
            unsigned long long acc = pk2(0.f, 0.f);
            #pragma unroll
            for (int j = 0; j < 32; j++) {
                float va = __shfl_sync(FULLM, fv.x, j);
                float vb = __shfl_sync(FULLM, fv.y, j);
                acc = fma2(pk2(va, va), w2[2 * j], acc);
                acc = fma2(pk2(vb, vb), w2[2 * j + 1], acc);
            }
            float r0, r1; unpk2(acc, r0, r1);
            atomicAdd(&out[pr.x * 64 + lane], r0);
            atomicAdd(&out[pr.x * 64 + 32 + lane], r1);
            pr = prn; k = kn; fv = fvn;
        }
    }
}

// ---------------- conv concat(32+32)->32 (decoder) ---------------------------
__global__ void convcat_center(const float* __restrict__ fA, const float* __restrict__ fB,
                               const float* __restrict__ W, float* __restrict__ out, int n) {
    int gw = (blockIdx.x * blockDim.x + threadIdx.x) >> 5;
    int lane = threadIdx.x & 31;
    int nw = (gridDim.x * blockDim.x) >> 5;
    float w[64];
    #pragma unroll
    for (int ci = 0; ci < 64; ci++) w[ci] = __ldg(&W[(13 * 64 + ci) * 32 + lane]);
    for (int v = gw; v < n; v += nw) {
        float fa = __ldg(&fA[v * 32 + lane]);
        float fb = __ldg(&fB[v * 32 + lane]);
        float acc = 0.f;
        #pragma unroll
        for (int ci = 0; ci < 32; ci++) acc = fmaf(__shfl_sync(FULLM, fa, ci), w[ci], acc);
        #pragma unroll
        for (int ci = 0; ci < 32; ci++) acc = fmaf(__shfl_sync(FULLM, fb, ci), w[32 + ci], acc);
        out[v * 32 + lane] = acc;
    }
}

__global__ void convcat_pair(const float* __restrict__ fA, const float* __restrict__ fB,
                             const float* __restrict__ W, float* __restrict__ out,
                             const int2* __restrict__ pairs,
                             const unsigned char* __restrict__ pk, const int* __restrict__ npp) {
    int gw = (blockIdx.x * blockDim.x + threadIdx.x) >> 5;
    int lane = threadIdx.x & 31;
    int nw = (gridDim.x * blockDim.x) >> 5;
    int np = *npp;
    float w[64];
    int kcur = -1;
    const int PPW = 32;
    for (int base = gw * PPW; base < np; base += nw * PPW) {
        int cnt = min(PPW, np - base);
        int2 pr = pairs[base];
        int k = pk[base];
        float fa = __ldg(&fA[pr.y * 32 + lane]);
        float fb = __ldg(&fB[pr.y * 32 + lane]);
        for (int m = 0; m < cnt; m++) {
            int2 prn = make_int2(0, 0); int kn = 0; float fan = 0.f, fbn = 0.f;
            if (m + 1 < cnt) {
                prn = pairs[base + m + 1];
                kn = pk[base + m + 1];
                fan = __ldg(&fA[prn.y * 32 + lane]);
                fbn = __ldg(&fB[prn.y * 32 + lane]);
            }
            if (k != kcur) {
                kcur = k;
                #pragma unroll
                for (int ci = 0; ci < 64; ci++) w[ci] = __ldg(&W[(k * 64 + ci) * 32 + lane]);
            }
            float acc = 0.f;
            #pragma unroll
            for (int ci = 0; ci < 32; ci++) acc = fmaf(__shfl_sync(FULLM, fa, ci), w[ci], acc);
            #pragma unroll
            for (int ci = 0; ci < 32; ci++) acc = fmaf(__shfl_sync(FULLM, fb, ci), w[32 + ci], acc);
            atomicAdd(&out[pr.x * 32 + lane], acc);
            pr = prn; k = kn; fa = fan; fb = fbn;
        }
    }
}

// ---------------- down: segment_sum(e0 @ W_down[coff], parent) ---------------
// lane owns output channels {2*lane, 2*lane+1}
__global__ void down_kernel(const float* __restrict__ e0, const int* __restrict__ parent,
                            const int* __restrict__ coff, const float* __restrict__ Wd,
                            float* __restrict__ down, int n) {
    int gw = (blockIdx.x * blockDim.x + threadIdx.x) >> 5;
    int lane = threadIdx.x & 31;
    int nw = (gridDim.x * blockDim.x) >> 5;
    for (int v = gw; v < n; v += nw) {
        float f = __ldg(&e0[v * 32 + lane]);
        const float* Wc = Wd + coff[v] * 2048;
        unsigned long long acc = pk2(0.f, 0.f);
        #pragma unroll
        for (int ci = 0; ci < 32; ci++) {
            float x = __shfl_sync(FULLM, f, ci);
            float2 wv = *(const float2*)(Wc + ci * 64 + 2 * lane);
            acc = fma2(pk2(x, x), pk2(wv.x, wv.y), acc);
        }
        float r0, r1; unpk2(acc, r0, r1);
        int p = parent[v];
        atomicAdd(&down[p * 64 + 2 * lane], r0);
        atomicAdd(&down[p * 64 + 2 * lane + 1], r1);
    }
}

// ---------------- up: e1[parent] @ W_up[coff] --------------------------------
__global__ void up_kernel(const float* __restrict__ e1, const int* __restrict__ parent,
                          const int* __restrict__ coff, const float* __restrict__ Wu,
                          float* __restrict__ up, int n) {
    int gw = (blockIdx.x * blockDim.x + threadIdx.x) >> 5;
    int lane = threadIdx.x & 31;
    int nw = (gridDim.x * blockDim.x) >> 5;
    for (int v = gw; v < n; v += nw) {
        int p = parent[v];
        float f0 = __ldg(&e1[p * 64 + lane]);
        float f1 = __ldg(&e1[p * 64 + 32 + lane]);
        const float* Wc = Wu + coff[v] * 2048;
        float acc = 0.f;
        #pragma unroll
        for (int ci = 0; ci < 32; ci++)
            acc = fmaf(__shfl_sync(FULLM, f0, ci), __ldg(&Wc[ci * 32 + lane]), acc);
        #pragma unroll
        for (int ci = 0; ci < 32; ci++)
            acc = fmaf(__shfl_sync(FULLM, f1, ci), __ldg(&Wc[(32 + ci) * 32 + lane]), acc);
        up[v * 32 + lane] = acc;
    }
}

// ---------------- batchnorm stats (float4) -----------------------------------
__global__ void bn_stats(const float* __restrict__ x, int bnid, int C, int n) {
    int C4 = C >> 2;
    int tid = threadIdx.x;
    int c4 = tid & (C4 - 1);
    int rpb = blockDim.x / C4;
    float s0 = 0, s1 = 0, s2 = 0, s3 = 0, q0 = 0, q1 = 0, q2 = 0, q3 = 0;
    for (long r = (long)blockIdx.x * rpb + tid / C4; r < n; r += (long)gridDim.x * rpb) {
        float4 v = *(const float4*)(x + r * C + c4 * 4);
        s0 += v.x; q0 += v.x * v.x;
        s1 += v.y; q1 += v.y * v.y;
        s2 += v.z; q2 += v.z * v.z;
        s3 += v.w; q3 += v.w * v.w;
    }
    __shared__ float ss[64], sq[64];
    if (tid < 64) { ss[tid] = 0.f; sq[tid] = 0.f; }
    __syncthreads();
    int cb = c4 * 4;
    atomicAdd(&ss[cb], s0); atomicAdd(&ss[cb + 1], s1);
    atomicAdd(&ss[cb + 2], s2); atomicAdd(&ss[cb + 3], s3);
    atomicAdd(&sq[cb], q0); atomicAdd(&sq[cb + 1], q1);
    atomicAdd(&sq[cb + 2], q2); atomicAdd(&sq[cb + 3], q3);
    __syncthreads();
    if (tid < C) {
        atomicAdd(&g_bn[bnid * 128 + tid], ss[tid]);
        atomicAdd(&g_bn[bnid * 128 + 64 + tid], sq[tid]);
    }
}

// ---------------- batchnorm apply + relu (float4, in place) ------------------
__global__ void bn_apply(float* __restrict__ x, const float* __restrict__ g,
                         const float* __restrict__ b, int bnid, int C, int n) {
    int C4 = C >> 2;
    float inv_n = 1.0f / (float)n;
    long total4 = (long)n * C4;
    long stride = (long)gridDim.x * blockDim.x;
    for (long i = (long)blockIdx.x * blockDim.x + threadIdx.x; i < total4; i += stride) {
        int cb = (int)(i & (C4 - 1)) * 4;
        float4 v = ((const float4*)x)[i];
        float* vp = &v.x;
        #pragma unroll
        for (int j = 0; j < 4; j++) {
            int c = cb + j;
            float mu = g_bn[bnid * 128 + c] * inv_n;
            float var = g_bn[bnid * 128 + 64 + c] * inv_n - mu * mu;
            float r = (vp[j] - mu) * rsqrtf(var + BN_EPS) * __ldg(&g[c]) + __ldg(&b[c]);
            vp[j] = r > 0.f ? r : 0.f;
        }
        ((float4*)x)[i] = v;
    }
}

// ---------------- final: bnrelu(dec) -> feature; y = feature@W_lin + b ------
__global__ void final_kernel(const float* __restrict__ dec, const float* __restrict__ g,
                             const float* __restrict__ b, const float* __restrict__ Wlin,
                             const float* __restrict__ blin, float* __restrict__ y,
                             float* __restrict__ fout, int n) {
    int gw = (blockIdx.x * blockDim.x + threadIdx.x) >> 5;
    int lane = threadIdx.x & 31;
    int nw = (gridDim.x * blockDim.x) >> 5;
    float wl[32];
    #pragma unroll
    for (int ci = 0; ci < 32; ci++) wl[ci] = (lane < 20) ? __ldg(&Wlin[ci * 20 + lane]) : 0.f;
    float bl = (lane < 20) ? __ldg(&blin[lane]) : 0.f;
    float inv_n = 1.0f / (float)n;
    float mu = g_bn[2 * 128 + lane] * inv_n;
    float var = g_bn[2 * 128 + 64 + lane] * inv_n - mu * mu;
    float rs = rsqrtf(var + BN_EPS) * __ldg(&g[lane]);
    float br = __ldg(&b[lane]);
    for (int v = gw; v < n; v += nw) {
        float f = (__ldg(&dec[v * 32 + lane]) - mu) * rs + br;
        f = f > 0.f ? f : 0.f;
        fout[v * 32 + lane] = f;
        float acc = bl;
        #pragma unroll
        for (int ci = 0; ci < 32; ci++) acc = fmaf(__shfl_sync(FULLM, f, ci), wl[ci], acc);
        if (lane < 20) y[v * 20 + lane] = acc;
    }
}

// ---------------- launcher ---------------------------------------------------
extern "C" void kernel_launch(void* const* d_in, const int* in_sizes, int n_in,
                              void* d_out, int out_size) {
    const float* feats      = (const float*)d_in[0];
    const int*   nbr_fine   = (const int*)  d_in[1];
    const int*   nbr_coarse = (const int*)  d_in[2];
    const int*   parent     = (const int*)  d_in[3];
    const int*   coff       = (const int*)  d_in[4];
    const float* W_sub      = (const float*)d_in[5];
    const float* W_e0       = (const float*)d_in[6];
    const float* g0         = (const float*)d_in[7];
    const float* b0         = (const float*)d_in[8];
    const float* W_down     = (const float*)d_in[9];
    const float* W_e1       = (const float*)d_in[10];
    const float* g1         = (const float*)d_in[11];
    const float* b1         = (const float*)d_in[12];
    const float* W_up       = (const float*)d_in[13];
    const float* W_dec      = (const float*)d_in[14];
    const float* g_outp     = (const float*)d_in[15];
    const float* b_outp     = (const float*)d_in[16];
    const float* W_lin      = (const float*)d_in[17];
    const float* b_lin      = (const float*)d_in[18];

    int N = in_sizes[0] / 3;
    int M = in_sizes[2] / 27;

    float* y    = (float*)d_out;
    float* fout = y + (long)N * 20;

    float *p_xv, *p_e0, *p_down, *p_e1, *p_up, *p_dec;
    int2 *p_pf, *p_pc; unsigned char *p_pfk, *p_pck; int *p_np;
    cudaGetSymbolAddress((void**)&p_xv,   g_xv);
    cudaGetSymbolAddress((void**)&p_e0,   g_e0);
    cudaGetSymbolAddress((void**)&p_down, g_down);
    cudaGetSymbolAddress((void**)&p_e1,   g_e1);
    cudaGetSymbolAddress((void**)&p_up,   g_up);
    cudaGetSymbolAddress((void**)&p_dec,  g_dec);
    cudaGetSymbolAddress((void**)&p_pf,   g_pf);
    cudaGetSymbolAddress((void**)&p_pc,   g_pc);
    cudaGetSymbolAddress((void**)&p_pfk,  g_pfk);
    cudaGetSymbolAddress((void**)&p_pck,  g_pck);
    cudaGetSymbolAddress((void**)&p_np,   g_np);

    dim3 b256(256), b128(128);
    int GP = 1024;      // persistent grids (light kernels, 256 thr)
    int GH = 2048;      // heavy 64ch kernels, 128 thr

    zero_kernel<<<1024, b256>>>(M);

    // pair lists
    hist_pairs<<<GP, b256>>>(nbr_fine,   N * 27, 0);
    hist_pairs<<<GP, b256>>>(nbr_coarse, M * 27, 1);
    scan_kernel<<<1, 32>>>();
    fill_pairs<<<GP, b256>>>(nbr_fine,   N * 27, 0, p_pf, p_pfk);
    fill_pairs<<<GP, b256>>>(nbr_coarse, M * 27, 1, p_pc, p_pck);

    // encoder fine level
    conv3_center<<<GP, b256>>>(feats, W_sub, p_xv, N);
    conv3_pair  <<<GP, b256>>>(feats, W_sub, p_xv, p_pf, p_pfk, p_np + 0);
    conv32_center<<<GP, b256>>>(p_xv, W_e0, p_e0, N);
    conv32_pair  <<<GP, b256>>>(p_xv, W_e0, p_e0, p_pf, p_pfk, p_np + 0);
    bn_stats<<<GP, b256>>>(p_e0, 0, 32, N);
    bn_apply<<<GP, b256>>>(p_e0, g0, b0, 0, 32, N);

    // down + coarse level
    down_kernel<<<GP, b256>>>(p_e0, parent, coff, W_down, p_down, N);
    conv64_center<<<GH, b128>>>(p_down, W_e1, p_e1, M);
    conv64_pair  <<<GH, b128>>>(p_down, W_e1, p_e1, p_pc, p_pck, p_np + 1);
    bn_stats<<<GP, b256>>>(p_e1, 1, 64, M);
    bn_apply<<<GP, b256>>>(p_e1, g1, b1, 1, 64, M);

    // up + decoder
    up_kernel<<<GP, b256>>>(p_e1, parent, coff, W_up, p_up, N);
    convcat_center<<<GP, b256>>>(p_e0, p_up, W_dec, p_dec, N);
    convcat_pair  <<<GP, b256>>>(p_e0, p_up, W_dec, p_dec, p_pf, p_pfk, p_np + 0);
    bn_stats<<<GP, b256>>>(p_dec, 2, 32, N);

    // fused bnrelu + linear head, writes both outputs
    final_kernel<<<GP, b256>>>(p_dec, g_outp, b_outp, W_lin, b_lin, y, fout, N);
}

// round 4
// speedup vs baseline: 1.3742x; 1.2512x over previous
#include <cuda_runtime.h>

#define MAXN 400000
#define MAXPAIR (MAXN * 26)
#define BN_EPS 1e-4f
#define FULLM 0xffffffffu

// ---------------- scratch (device globals; no allocations allowed) ----------
__device__ float g_xv  [(size_t)MAXN * 32];
__device__ float g_e0  [(size_t)MAXN * 32];
__device__ float g_down[(size_t)MAXN * 64];
__device__ float g_e1  [(size_t)MAXN * 64];
__device__ float g_up  [(size_t)MAXN * 32];
__device__ float g_dec [(size_t)MAXN * 32];
__device__ float g_bn[3 * 128];            // per-bn: [0:64) sums, [64:128) sumsq

__device__ int2          g_pf [MAXPAIR];   // fine pairs (dst, src), grouped by k
__device__ unsigned char g_pfk[MAXPAIR];
__device__ int2          g_pc [MAXPAIR];   // coarse pairs
__device__ unsigned char g_pck[MAXPAIR];
__device__ int g_cnt[64];                  // [lvl*32 + k] histogram
__device__ int g_cur[64];                  // allocation cursors (start at offsets)
__device__ int g_np [2];                   // total pairs per level

// ---------------- f32x2 helpers ---------------------------------------------
__device__ __forceinline__ unsigned long long pk2(float x, float y) {
    unsigned long long r;
    asm("mov.b64 %0, {%1, %2};" : "=l"(r) : "f"(x), "f"(y));
    return r;
}
__device__ __forceinline__ unsigned long long fma2(unsigned long long a,
                                                   unsigned long long b,
                                                   unsigned long long c) {
    unsigned long long d;
    asm("fma.rn.f32x2 %0, %1, %2, %3;" : "=l"(d) : "l"(a), "l"(b), "l"(c));
    return d;
}
__device__ __forceinline__ void unpk2(unsigned long long a, float& x, float& y) {
    asm("mov.b64 {%0, %1}, %2;" : "=f"(x), "=f"(y) : "l"(a));
}

// ---------------- zero: g_down rows, bn accumulators, histograms ------------
__global__ void zero_kernel(int m) {
    int tid = blockIdx.x * blockDim.x + threadIdx.x;
    int stride = gridDim.x * blockDim.x;
    float4* d4 = (float4*)g_down;
    int n4 = m * 16;
    for (int i = tid; i < n4; i += stride) d4[i] = make_float4(0.f, 0.f, 0.f, 0.f);
    if (blockIdx.x == 0 && threadIdx.x < 128) {
        g_bn[threadIdx.x] = 0.f; g_bn[128 + threadIdx.x] = 0.f; g_bn[256 + threadIdx.x] = 0.f;
        if (threadIdx.x < 64) g_cnt[threadIdx.x] = 0;
    }
}

// ---------------- histogram (both levels, smem-aggregated) -------------------
__global__ void hist_all(const int* __restrict__ nbrF, int n27F,
                         const int* __restrict__ nbrC, int n27C) {
    __shared__ int sh[64];
    if (threadIdx.x < 64) sh[threadIdx.x] = 0;
    __syncthreads();
    int tid = blockIdx.x * blockDim.x + threadIdx.x;
    int stride = gridDim.x * blockDim.x;
    for (int i = tid; i < n27F; i += stride) {
        int k = i % 27;
        if (k != 13 && nbrF[i] >= 0) atomicAdd(&sh[k], 1);
    }
    for (int i = tid; i < n27C; i += stride) {
        int k = i % 27;
        if (k != 13 && nbrC[i] >= 0) atomicAdd(&sh[32 + k], 1);
    }
    __syncthreads();
    if (threadIdx.x < 64 && sh[threadIdx.x] > 0) atomicAdd(&g_cnt[threadIdx.x], sh[threadIdx.x]);
}

__global__ void scan_kernel() {
    if (threadIdx.x == 0) {
        for (int l = 0; l < 2; l++) {
            int s = 0;
            for (int k = 0; k < 27; k++) {
                g_cur[l * 32 + k] = s;
                s += g_cnt[l * 32 + k];
            }
            g_np[l] = s;
        }
    }
}

// ---------------- fill pairs: block-tile aggregated reservations -------------
#define FILL_TILE 32768
__global__ void fill_all(const int* __restrict__ nbrF, int n27F, int tilesF,
                         const int* __restrict__ nbrC, int n27C,
                         int2* __restrict__ pf, unsigned char* __restrict__ pfk,
                         int2* __restrict__ pc, unsigned char* __restrict__ pck) {
    int lvl, tile, n27;
    const int* nbr;
    int2* pairs; unsigned char* pk;
    if ((int)blockIdx.x < tilesF) {
        lvl = 0; tile = blockIdx.x; nbr = nbrF; n27 = n27F; pairs = pf; pk = pfk;
    } else {
        lvl = 1; tile = blockIdx.x - tilesF; nbr = nbrC; n27 = n27C; pairs = pc; pk = pck;
    }
    int start = tile * FILL_TILE;
    int end = min(start + FILL_TILE, n27);
    __shared__ int cnt[27], cur[27];
    if (threadIdx.x < 27) cnt[threadIdx.x] = 0;
    __syncthreads();
    for (int i = start + threadIdx.x; i < end; i += blockDim.x) {
        int k = i % 27;
        if (k != 13 && nbr[i] >= 0) atomicAdd(&cnt[k], 1);
    }
    __syncthreads();
    if (threadIdx.x < 27 && cnt[threadIdx.x] > 0)
        cur[threadIdx.x] = atomicAdd(&g_cur[lvl * 32 + threadIdx.x], cnt[threadIdx.x]);
    __syncthreads();
    for (int i = start + threadIdx.x; i < end; i += blockDim.x) {
        int k = i % 27;
        int idx = nbr[i];
        if (k != 13 && idx >= 0) {
            int pos = atomicAdd(&cur[k], 1);
            pairs[pos] = make_int2(i / 27, idx);
            pk[pos] = (unsigned char)k;
        }
    }
}

// ---------------- conv 3->32 -------------------------------------------------
__global__ void conv3_center(const float* __restrict__ in, const float* __restrict__ W,
                             float* __restrict__ out, int n) {
    int gw = (blockIdx.x * blockDim.x + threadIdx.x) >> 5;
    int lane = threadIdx.x & 31;
    int nw = (gridDim.x * blockDim.x) >> 5;
    float w0 = __ldg(&W[(13 * 3 + 0) * 32 + lane]);
    float w1 = __ldg(&W[(13 * 3 + 1) * 32 + lane]);
    float w2 = __ldg(&W[(13 * 3 + 2) * 32 + lane]);
    for (int v = gw; v < n; v += nw) {
        float f = (lane < 3) ? __ldg(&in[v * 3 + lane]) : 0.f;
        float a = __shfl_sync(FULLM, f, 0) * w0;
        a = fmaf(__shfl_sync(FULLM, f, 1), w1, a);
        a = fmaf(__shfl_sync(FULLM, f, 2), w2, a);
        out[v * 32 + lane] = a;
    }
}

__global__ void conv3_pair(const float* __restrict__ in, const float* __restrict__ W,
                           float* __restrict__ out, const int2* __restrict__ pairs,
                           const unsigned char* __restrict__ pk, const int* __restrict__ npp) {
    int gw = (blockIdx.x * blockDim.x + threadIdx.x) >> 5;
    int lane = threadIdx.x & 31;
    int nw = (gridDim.x * blockDim.x) >> 5;
    int np = *npp;
    float w0 = 0.f, w1 = 0.f, w2 = 0.f;
    int kcur = -1;
    const int PPW = 32;
    for (int base = gw * PPW; base < np; base += nw * PPW) {
        int cnt = min(PPW, np - base);
        for (int m = 0; m < cnt; m++) {
            int2 pr = pairs[base + m];
            int k = pk[base + m];
            if (k != kcur) {
                kcur = k;
                w0 = __ldg(&W[(k * 3 + 0) * 32 + lane]);
                w1 = __ldg(&W[(k * 3 + 1) * 32 + lane]);
                w2 = __ldg(&W[(k * 3 + 2) * 32 + lane]);
            }
            float f = (lane < 3) ? __ldg(&in[pr.y * 3 + lane]) : 0.f;
            float a = __shfl_sync(FULLM, f, 0) * w0;
            a = fmaf(__shfl_sync(FULLM, f, 1), w1, a);
            a = fmaf(__shfl_sync(FULLM, f, 2), w2, a);
            atomicAdd(&out[pr.x * 32 + lane], a);
        }
    }
}

// ---------------- conv 32->32 ------------------------------------------------
__global__ void conv32_center(const float* __restrict__ in, const float* __restrict__ W,
                              float* __restrict__ out, int n) {
    int gw = (blockIdx.x * blockDim.x + threadIdx.x) >> 5;
    int lane = threadIdx.x & 31;
    int nw = (gridDim.x * blockDim.x) >> 5;
    float w[32];
    #pragma unroll
    for (int ci = 0; ci < 32; ci++) w[ci] = __ldg(&W[(13 * 32 + ci) * 32 + lane]);
    for (int v = gw; v < n; v += nw) {
        float f = __ldg(&in[v * 32 + lane]);
        float acc = 0.f;
        #pragma unroll
        for (int ci = 0; ci < 32; ci++) acc = fmaf(__shfl_sync(FULLM, f, ci), w[ci], acc);
        out[v * 32 + lane] = acc;
    }
}

__global__ void conv32_pair(const float* __restrict__ in, const float* __restrict__ W,
                            float* __restrict__ out, const int2* __restrict__ pairs,
                            const unsigned char* __restrict__ pk, const int* __restrict__ npp) {
    int gw = (blockIdx.x * blockDim.x + threadIdx.x) >> 5;
    int lane = threadIdx.x & 31;
    int nw = (gridDim.x * blockDim.x) >> 5;
    int np = *npp;
    float w[32];
    int kcur = -1;
    const int PPW = 32;
    for (int base = gw * PPW; base < np; base += nw * PPW) {
        int cnt = min(PPW, np - base);
        int2 pr = pairs[base];
        int k = pk[base];
        float f = __ldg(&in[pr.y * 32 + lane]);
        for (int m = 0; m < cnt; m++) {
            int2 prn = make_int2(0, 0); int kn = 0; float fn = 0.f;
            if (m + 1 < cnt) {
                prn = pairs[base + m + 1];
                kn = pk[base + m + 1];
                fn = __ldg(&in[prn.y * 32 + lane]);
            }
            if (k != kcur) {
                kcur = k;
                #pragma unroll
                for (int ci = 0; ci < 32; ci++) w[ci] = __ldg(&W[(k * 32 + ci) * 32 + lane]);
            }
            float acc = 0.f;
            #pragma unroll
            for (int ci = 0; ci < 32; ci++) acc = fmaf(__shfl_sync(FULLM, f, ci), w[ci], acc);
            atomicAdd(&out[pr.x * 32 + lane], acc);
            pr = prn; k = kn; f = fn;
        }
    }
}

// ---------------- conv 64->64 (coarse), f32x2 packed -------------------------
__global__ void __launch_bounds__(128)
conv64_center(const float* __restrict__ in, const float* __restrict__ W,
              float* __restrict__ out, int n) {
    int gw = (blockIdx.x * blockDim.x + threadIdx.x) >> 5;
    int lane = threadIdx.x & 31;
    int nw = (gridDim.x * blockDim.x) >> 5;
    unsigned long long w2[64];
    #pragma unroll
    for (int ci = 0; ci < 64; ci++) {
        float a = __ldg(&W[(13 * 64 + ci) * 64 + lane]);
        float b = __ldg(&W[(13 * 64 + ci) * 64 + 32 + lane]);
        w2[ci] = pk2(a, b);
    }
    for (int v = gw; v < n; v += nw) {
        float2 fv = *(const float2*)(in + v * 64 + 2 * lane);
        unsigned long long acc = pk2(0.f, 0.f);
        #pragma unroll
        for (int j = 0; j < 32; j++) {
            float va = __shfl_sync(FULLM, fv.x, j);
            float vb = __shfl_sync(FULLM, fv.y, j);
            acc = fma2(pk2(va, va), w2[2 * j], acc);
            acc = fma2(pk2(vb, vb), w2[2 * j + 1], acc);
        }
        float r0, r1; unpk2(acc, r0, r1);
        out[v * 64 + lane] = r0;
        out[v * 64 + 32 + lane] = r1;
    }
}

__global__ void __launch_bounds__(128)
conv64_pair(const float* __restrict__ in, const float* __restrict__ W,
            float* __restrict__ out, const int2* __restrict__ pairs,
            const unsigned char* __restrict__ pk, const int* __restrict__ npp) {
    int gw = (blockIdx.x * blockDim.x + threadIdx.x) >> 5;
    int lane = threadIdx.x & 31;
    int nw = (gridDim.x * blockDim.x) >> 5;
    int np = *npp;
    unsigned long long w2[64];
    int kcur = -1;
    const int PPW = 32;
    for (int base = gw * PPW; base < np; base += nw * PPW) {
        int cnt = min(PPW, np - base);
        int2 pr = pairs[base];
        int k = pk[base];
        float2 fv = *(const float2*)(in + pr.y * 64 + 2 * lane);
        for (int m = 0; m < cnt; m++) {
            int2 prn = make_int2(0, 0); int kn = 0; float2 fvn = make_float2(0.f, 0.f);
            if (m + 1 < cnt) {
                prn = pairs[base + m + 1];
                kn = pk[base + m + 1];
                fvn = *(const float2*)(in + prn.y * 64 + 2 * lane);
            }
            if (k != kcur) {
                kcur = k;
                #pragma unroll
                for (int ci = 0; ci < 64; ci++) {
                    float a = __ldg(&W[(k * 64 + ci) * 64 + lane]);
                    float b = __ldg(&W[(k * 64 + ci) * 64 + 32 + lane]);
                    w2[ci] = pk2(a, b);
                }
            }
            unsigned long long acc = pk2(0.f, 0.f);
            #pragma unroll
            for (int j = 0; j < 32; j++) {
                float va = __shfl_sync(FULLM, fv.x, j);
                float vb = __shfl_sync(FULLM, fv.y, j);
                acc = fma2(pk2(va, va), w2[2 * j], acc);
                acc = fma2(pk2(vb, vb), w2[2 * j + 1], acc);
            }
            float r0, r1; unpk2(acc, r0, r1);
            atomicAdd(&out[pr.x * 64 + lane], r0);
            atomicAdd(&out[pr.x * 64 + 32 + lane], r1);
            pr = prn; k = kn; fv = fvn;
        }
    }
}

// ---------------- conv concat(bnrelu(e0) + up)->32 (decoder) -----------------
__global__ void convcat_center(const float* __restrict__ fA, const float* __restrict__ fB,
                               const float* __restrict__ W,
                               const float* __restrict__ g0, const float* __restrict__ b0,
                               float* __restrict__ out, int n, float inv_n) {
    int gw = (blockIdx.x * blockDim.x + threadIdx.x) >> 5;
    int lane = threadIdx.x & 31;
    int nw = (gridDim.x * blockDim.x) >> 5;
    float mu = g_bn[lane] * inv_n;
    float var = g_bn[64 + lane] * inv_n - mu * mu;
    float rs = rsqrtf(var + BN_EPS) * __ldg(&g0[lane]);
    float bb = __ldg(&b0[lane]);
    float w[64];
    #pragma unroll
    for (int ci = 0; ci < 64; ci++) w[ci] = __ldg(&W[(13 * 64 + ci) * 32 + lane]);
    for (int v = gw; v < n; v += nw) {
        float fa = (__ldg(&fA[v * 32 + lane]) - mu) * rs + bb;
        fa = fa > 0.f ? fa : 0.f;
        float fb = __ldg(&fB[v * 32 + lane]);
        float acc = 0.f;
        #pragma unroll
        for (int ci = 0; ci < 32; ci++) acc = fmaf(__shfl_sync(FULLM, fa, ci), w[ci], acc);
        #pragma unroll
        for (int ci = 0; ci < 32; ci++) acc = fmaf(__shfl_sync(FULLM, fb, ci), w[32 + ci], acc);
        out[v * 32 + lane] = acc;
    }
}

__global__ void convcat_pair(const float* __restrict__ fA, const float* __restrict__ fB,
                             const float* __restrict__ W,
                             const float* __restrict__ g0, const float* __restrict__ b0,
                             float* __restrict__ out, const int2* __restrict__ pairs,
                             const unsigned char* __restrict__ pk, const int* __restrict__ npp,
                             float inv_n) {
    int gw = (blockIdx.x * blockDim.x + threadIdx.x) >> 5;
    int lane = threadIdx.x & 31;
    int nw = (gridDim.x * blockDim.x) >> 5;
    int np = *npp;
    float mu = g_bn[lane] * inv_n;
    float var = g_bn[64 + lane] * inv_n - mu * mu;
    float rs = rsqrtf(var + BN_EPS) * __ldg(&g0[lane]);
    float bb = __ldg(&b0[lane]);
    float w[64];
    int kcur = -1;
    const int PPW = 32;
    for (int base = gw * PPW; base < np; base += nw * PPW) {
        int cnt = min(PPW, np - base);
        int2 pr = pairs[base];
        int k = pk[base];
        float fa = __ldg(&fA[pr.y * 32 + lane]);
        float fb = __ldg(&fB[pr.y * 32 + lane]);
        for (int m = 0; m < cnt; m++) {
            int2 prn = make_int2(0, 0); int kn = 0; float fan = 0.f, fbn = 0.f;
            if (m + 1 < cnt) {
                prn = pairs[base + m + 1];
                kn = pk[base + m + 1];
                fan = __ldg(&fA[prn.y * 32 + lane]);
                fbn = __ldg(&fB[prn.y * 32 + lane]);
            }
            if (k != kcur) {
                kcur = k;
                #pragma unroll
                for (int ci = 0; ci < 64; ci++) w[ci] = __ldg(&W[(k * 64 + ci) * 32 + lane]);
            }
            float fav = (fa - mu) * rs + bb;
            fav = fav > 0.f ? fav : 0.f;
            float acc = 0.f;
            #pragma unroll
            for (int ci = 0; ci < 32; ci++) acc = fmaf(__shfl_sync(FULLM, fav, ci), w[ci], acc);
            #pragma unroll
            for (int ci = 0; ci < 32; ci++) acc = fmaf(__shfl_sync(FULLM, fb, ci), w[32 + ci], acc);
            atomicAdd(&out[pr.x * 32 + lane], acc);
            pr = prn; k = kn; fa = fan; fb = fbn;
        }
    }
}

// ---------------- down: segment_sum(bnrelu(e0) @ W_down[coff], parent) -------
// weights staged in 64KB dynamic smem; BN(e0) inline. lane owns couts {2l,2l+1}
__global__ void down_smem(const float* __restrict__ e0, const int* __restrict__ parent,
                          const int* __restrict__ coff, const float* __restrict__ Wd,
                          const float* __restrict__ g0, const float* __restrict__ b0,
                          float* __restrict__ down, int n, float inv_n) {
    extern __shared__ float sw[];
    for (int j = threadIdx.x; j < 8 * 2048 / 4; j += blockDim.x)
        ((float4*)sw)[j] = ((const float4*)Wd)[j];
    __syncthreads();
    int gw = (blockIdx.x * blockDim.x + threadIdx.x) >> 5;
    int lane = threadIdx.x & 31;
    int nw = (gridDim.x * blockDim.x) >> 5;
    float mu = g_bn[lane] * inv_n;
    float var = g_bn[64 + lane] * inv_n - mu * mu;
    float rs = rsqrtf(var + BN_EPS) * __ldg(&g0[lane]);
    float bb = __ldg(&b0[lane]);
    for (int v = gw; v < n; v += nw) {
        float f = (__ldg(&e0[v * 32 + lane]) - mu) * rs + bb;
        f = f > 0.f ? f : 0.f;
        const float* Wc = sw + coff[v] * 2048;
        unsigned long long acc = pk2(0.f, 0.f);
        #pragma unroll
        for (int ci = 0; ci < 32; ci++) {
            float x = __shfl_sync(FULLM, f, ci);
            float2 wv = *(const float2*)(Wc + ci * 64 + 2 * lane);
            acc = fma2(pk2(x, x), pk2(wv.x, wv.y), acc);
        }
        float r0, r1; unpk2(acc, r0, r1);
        int p = parent[v];
        atomicAdd(&down[p * 64 + 2 * lane], r0);
        atomicAdd(&down[p * 64 + 2 * lane + 1], r1);
    }
}

// ---------------- up: bnrelu(e1)[parent] @ W_up[coff] ------------------------
__global__ void up_smem(const float* __restrict__ e1, const int* __restrict__ parent,
                        const int* __restrict__ coff, const float* __restrict__ Wu,
                        const float* __restrict__ g1, const float* __restrict__ b1,
                        float* __restrict__ up, int n, float inv_m) {
    extern __shared__ float sw[];
    for (int j = threadIdx.x; j < 8 * 2048 / 4; j += blockDim.x)
        ((float4*)sw)[j] = ((const float4*)Wu)[j];
    __syncthreads();
    int gw = (blockIdx.x * blockDim.x + threadIdx.x) >> 5;
    int lane = threadIdx.x & 31;
    int nw = (gridDim.x * blockDim.x) >> 5;
    float muA = g_bn[128 + lane] * inv_m;
    float vaA = g_bn[128 + 64 + lane] * inv_m - muA * muA;
    float rsA = rsqrtf(vaA + BN_EPS) * __ldg(&g1[lane]);
    float bbA = __ldg(&b1[lane]);
    float muB = g_bn[128 + 32 + lane] * inv_m;
    float vaB = g_bn[128 + 64 + 32 + lane] * inv_m - muB * muB;
    float rsB = rsqrtf(vaB + BN_EPS) * __ldg(&g1[32 + lane]);
    float bbB = __ldg(&b1[32 + lane]);
    for (int v = gw; v < n; v += nw) {
        int p = parent[v];
        float f0 = (__ldg(&e1[p * 64 + lane]) - muA) * rsA + bbA;
        f0 = f0 > 0.f ? f0 : 0.f;
        float f1 = (__ldg(&e1[p * 64 + 32 + lane]) - muB) * rsB + bbB;
        f1 = f1 > 0.f ? f1 : 0.f;
        const float* Wc = sw + coff[v] * 2048;
        float acc = 0.f;
        #pragma unroll
        for (int ci = 0; ci < 32; ci++)
            acc = fmaf(__shfl_sync(FULLM, f0, ci), Wc[ci * 32 + lane], acc);
        #pragma unroll
        for (int ci = 0; ci < 32; ci++)
            acc = fmaf(__shfl_sync(FULLM, f1, ci), Wc[(32 + ci) * 32 + lane], acc);
        up[v * 32 + lane] = acc;
    }
}

// ---------------- batchnorm stats (float4) -----------------------------------
__global__ void bn_stats(const float* __restrict__ x, int bnid, int C, int n) {
    int C4 = C >> 2;
    int tid = threadIdx.x;
    int c4 = tid & (C4 - 1);
    int rpb = blockDim.x / C4;
    float s0 = 0, s1 = 0, s2 = 0, s3 = 0, q0 = 0, q1 = 0, q2 = 0, q3 = 0;
    for (long r = (long)blockIdx.x * rpb + tid / C4; r < n; r += (long)gridDim.x * rpb) {
        float4 v = *(const float4*)(x + r * C + c4 * 4);
        s0 += v.x; q0 += v.x * v.x;
        s1 += v.y; q1 += v.y * v.y;
        s2 += v.z; q2 += v.z * v.z;
        s3 += v.w; q3 += v.w * v.w;
    }
    __shared__ float ss[64], sq[64];
    if (tid < 64) { ss[tid] = 0.f; sq[tid] = 0.f; }
    __syncthreads();
    int cb = c4 * 4;
    atomicAdd(&ss[cb], s0); atomicAdd(&ss[cb + 1], s1);
    atomicAdd(&ss[cb + 2], s2); atomicAdd(&ss[cb + 3], s3);
    atomicAdd(&sq[cb], q0); atomicAdd(&sq[cb + 1], q1);
    atomicAdd(&sq[cb + 2], q2); atomicAdd(&sq[cb + 3], q3);
    __syncthreads();
    if (tid < C) {
        atomicAdd(&g_bn[bnid * 128 + tid], ss[tid]);
        atomicAdd(&g_bn[bnid * 128 + 64 + tid], sq[tid]);
    }
}

// ---------------- final: bnrelu(dec) -> feature; y = feature@W_lin + b ------
__global__ void final_kernel(const float* __restrict__ dec, const float* __restrict__ g,
                             const float* __restrict__ b, const float* __restrict__ Wlin,
                             const float* __restrict__ blin, float* __restrict__ y,
                             float* __restrict__ fout, int n) {
    int gw = (blockIdx.x * blockDim.x + threadIdx.x) >> 5;
    int lane = threadIdx.x & 31;
    int nw = (gridDim.x * blockDim.x) >> 5;
    float wl[32];
    #pragma unroll
    for (int ci = 0; ci < 32; ci++) wl[ci] = (lane < 20) ? __ldg(&Wlin[ci * 20 + lane]) : 0.f;
    float bl = (lane < 20) ? __ldg(&blin[lane]) : 0.f;
    float inv_n = 1.0f / (float)n;
    float mu = g_bn[2 * 128 + lane] * inv_n;
    float var = g_bn[2 * 128 + 64 + lane] * inv_n - mu * mu;
    float rs = rsqrtf(var + BN_EPS) * __ldg(&g[lane]);
    float br = __ldg(&b[lane]);
    for (int v = gw; v < n; v += nw) {
        float f = (__ldg(&dec[v * 32 + lane]) - mu) * rs + br;
        f = f > 0.f ? f : 0.f;
        fout[v * 32 + lane] = f;
        float acc = bl;
        #pragma unroll
        for (int ci = 0; ci < 32; ci++) acc = fmaf(__shfl_sync(FULLM, f, ci), wl[ci], acc);
        if (lane < 20) y[v * 20 + lane] = acc;
    }
}

// ---------------- launcher ---------------------------------------------------
extern "C" void kernel_launch(void* const* d_in, const int* in_sizes, int n_in,
                              void* d_out, int out_size) {
    const float* feats      = (const float*)d_in[0];
    const int*   nbr_fine   = (const int*)  d_in[1];
    const int*   nbr_coarse = (const int*)  d_in[2];
    const int*   parent     = (const int*)  d_in[3];
    const int*   coff       = (const int*)  d_in[4];
    const float* W_sub      = (const float*)d_in[5];
    const float* W_e0       = (const float*)d_in[6];
    const float* g0         = (const float*)d_in[7];
    const float* b0         = (const float*)d_in[8];
    const float* W_down     = (const float*)d_in[9];
    const float* W_e1       = (const float*)d_in[10];
    const float* g1         = (const float*)d_in[11];
    const float* b1         = (const float*)d_in[12];
    const float* W_up       = (const float*)d_in[13];
    const float* W_dec      = (const float*)d_in[14];
    const float* g_outp     = (const float*)d_in[15];
    const float* b_outp     = (const float*)d_in[16];
    const float* W_lin      = (const float*)d_in[17];
    const float* b_lin      = (const float*)d_in[18];

    int N = in_sizes[0] / 3;
    int M = in_sizes[2] / 27;
    float inv_n = 1.0f / (float)N;
    float inv_m = 1.0f / (float)M;

    float* y    = (float*)d_out;
    float* fout = y + (long)N * 20;

    float *p_xv, *p_e0, *p_down, *p_e1, *p_up, *p_dec;
    int2 *p_pf, *p_pc; unsigned char *p_pfk, *p_pck; int *p_np;
    cudaGetSymbolAddress((void**)&p_xv,   g_xv);
    cudaGetSymbolAddress((void**)&p_e0,   g_e0);
    cudaGetSymbolAddress((void**)&p_down, g_down);
    cudaGetSymbolAddress((void**)&p_e1,   g_e1);
    cudaGetSymbolAddress((void**)&p_up,   g_up);
    cudaGetSymbolAddress((void**)&p_dec,  g_dec);
    cudaGetSymbolAddress((void**)&p_pf,   g_pf);
    cudaGetSymbolAddress((void**)&p_pc,   g_pc);
    cudaGetSymbolAddress((void**)&p_pfk,  g_pfk);
    cudaGetSymbolAddress((void**)&p_pck,  g_pck);
    cudaGetSymbolAddress((void**)&p_np,   g_np);

    static int smem_set = 0;
    cudaFuncSetAttribute(down_smem, cudaFuncAttributeMaxDynamicSharedMemorySize, 65536);
    cudaFuncSetAttribute(up_smem,   cudaFuncAttributeMaxDynamicSharedMemorySize, 65536);
    (void)smem_set;

    dim3 b256(256), b128(128);
    int GP = 1024;      // persistent grids (light kernels, 256 thr)
    int GH = 2048;      // heavy 64ch kernels, 128 thr
    int GD = 444;       // 64KB-smem kernels (3 blocks/SM)

    zero_kernel<<<1024, b256>>>(M);

    // pair lists (hist -> scan -> tile-aggregated fill)
    int n27F = N * 27, n27C = M * 27;
    hist_all<<<GP, b256>>>(nbr_fine, n27F, nbr_coarse, n27C);
    scan_kernel<<<1, 32>>>();
    int tilesF = (n27F + FILL_TILE - 1) / FILL_TILE;
    int tilesC = (n27C + FILL_TILE - 1) / FILL_TILE;
    fill_all<<<tilesF + tilesC, b256>>>(nbr_fine, n27F, tilesF, nbr_coarse, n27C,
                                        p_pf, p_pfk, p_pc, p_pck);

    // encoder fine level
    conv3_center<<<GP, b256>>>(feats, W_sub, p_xv, N);
    conv3_pair  <<<GP, b256>>>(feats, W_sub, p_xv, p_pf, p_pfk, p_np + 0);
    conv32_center<<<GP, b256>>>(p_xv, W_e0, p_e0, N);
    conv32_pair  <<<GP, b256>>>(p_xv, W_e0, p_e0, p_pf, p_pfk, p_np + 0);
    bn_stats<<<GP, b256>>>(p_e0, 0, 32, N);

    // down + coarse level (BN0 applied inline)
    down_smem<<<GD, b256, 65536>>>(p_e0, parent, coff, W_down, g0, b0, p_down, N, inv_n);
    conv64_center<<<GH, b128>>>(p_down, W_e1, p_e1, M);
    conv64_pair  <<<GH, b128>>>(p_down, W_e1, p_e1, p_pc, p_pck, p_np + 1);
    bn_stats<<<GP, b256>>>(p_e1, 1, 64, M);

    // up + decoder (BN1 / BN0 applied inline)
    up_smem<<<GD, b256, 65536>>>(p_e1, parent, coff, W_up, g1, b1, p_up, N, inv_m);
    convcat_center<<<GP, b256>>>(p_e0, p_up, W_dec, g0, b0, p_dec, N, inv_n);
    convcat_pair  <<<GP, b256>>>(p_e0, p_up, W_dec, g0, b0, p_dec, p_pf, p_pfk, p_np + 0, inv_n);
    bn_stats<<<GP, b256>>>(p_dec, 2, 32, N);

    // fused bnrelu + linear head, writes both outputs
    final_kernel<<<GP, b256>>>(p_dec, g_outp, b_outp, W_lin, b_lin, y, fout, N);
}